// round 2
// baseline (speedup 1.0000x reference)
#include <cuda_runtime.h>
#include <math.h>

// ---------------------------------------------------------------------------
// Encoder_conv2: 5-level grid encoder, fully fused single kernel.
//   per level: a = tanh(depthwise_conv3x3(F)); out_l = sum_cell bilinear(a[cell], p+0.5*cell)
// Merged-lattice trick: the 2-cell sum is piecewise bilinear on the half-integer
// lattice -> per level build G[(2r)^2][4ch]; one bilinear fetch per level/point.
// Every block redundantly builds the grids in its own smem (work is ~microscopic),
// then grid-strides over points with smem-staged coalesced output stores.
// ---------------------------------------------------------------------------

#define NLEV 5

// a texels cumulative: 2*r*r per level (r = 8,12,20,18,32)
#define ATEX0 0
#define ATEX1 128
#define ATEX2 416
#define ATEX3 1216
#define ATEX4 1864
#define ATEXT 3912
// G texels cumulative: (2r)^2 per level
#define GTEX0 0
#define GTEX1 256
#define GTEX2 832
#define GTEX3 2432
#define GTEX4 3728
#define GTEXT 7824

#define NTHR 512
// scratch region (after G): used for a4 during prologue (ATEXT float4),
// then reused for output staging (NTHR*5 float4). a4 is larger.
#define SCRATCH_F4 ATEXT
#define SMEM_F4 (GTEXT + SCRATCH_F4)
#define SMEM_BYTES (SMEM_F4 * 16)

__global__ void __launch_bounds__(NTHR, 1)
k_fused(const float* __restrict__ F0, const float* __restrict__ F1,
        const float* __restrict__ F2, const float* __restrict__ F3,
        const float* __restrict__ F4, const float* __restrict__ W,
        const float* __restrict__ X, const float* __restrict__ Y,
        float* __restrict__ out, int npts) {
    extern __shared__ float4 smem[];
    float4* sg = smem;              // merged grids, GTEXT float4
    float4* sa = smem + GTEXT;      // scratch: a4 then output staging

    const int tid = threadIdx.x;

    // load conv weights to registers (broadcast, 36 floats)
    float w[36];
    #pragma unroll
    for (int i = 0; i < 36; i++) w[i] = W[i];

    const int resa[5] = {8, 12, 20, 18, 32};
    const int acum[6] = {ATEX0, ATEX1, ATEX2, ATEX3, ATEX4, ATEXT};
    const int gcum[6] = {GTEX0, GTEX1, GTEX2, GTEX3, GTEX4, GTEXT};

    // ---- Phase 1a: depthwise conv3x3 (SAME, zero-pad) + tanh -> sa ----
    for (int tex = tid; tex < ATEXT; tex += NTHR) {
        int l = 0;
        #pragma unroll
        for (int q = 0; q < 4; q++) if (tex >= acum[q + 1]) l = q + 1;
        const float* Fl = (l == 0) ? F0 : (l == 1) ? F1 : (l == 2) ? F2 : (l == 3) ? F3 : F4;
        const int r = resa[l];
        int rem = tex - acum[l];
        int rr  = r * r;
        int j   = rem / rr;
        int yx  = rem - j * rr;
        int y   = yx / r;
        int x   = yx - y * r;

        float oc[4];
        #pragma unroll
        for (int c = 0; c < 4; c++) {
            float s = 0.f;
            #pragma unroll
            for (int dy = 0; dy < 3; dy++) {
                int yy = y + dy - 1;
                if (yy < 0 || yy >= r) continue;
                #pragma unroll
                for (int dx = 0; dx < 3; dx++) {
                    int xx = x + dx - 1;
                    if (xx < 0 || xx >= r) continue;
                    s += __ldg(&Fl[((j * 4 + c) * r + yy) * r + xx]) * w[c * 9 + dy * 3 + dx];
                }
            }
            oc[c] = tanhf(s);
        }
        sa[tex] = make_float4(oc[0], oc[1], oc[2], oc[3]);
    }
    __syncthreads();

    // ---- Phase 1b: merged half-lattice node grid -> sg ----
    // G[k][m] = sum_j bilinear_clamped(a[j], (m+j)/2, (k+j)/2)
    for (int tex = tid; tex < GTEXT; tex += NTHR) {
        int l = 0;
        #pragma unroll
        for (int q = 0; q < 4; q++) if (tex >= gcum[q + 1]) l = q + 1;
        const int r  = resa[l];
        const int n2 = 2 * r;
        int rem = tex - gcum[l];
        int k   = rem / n2;
        int m   = rem - k * n2;

        float ax = 0.f, ay = 0.f, az = 0.f, aw = 0.f;
        #pragma unroll
        for (int j = 0; j < 2; j++) {
            float px = 0.5f * (float)(m + j);
            float py = 0.5f * (float)(k + j);
            float fx = floorf(px), fy = floorf(py);
            float wx = px - fx,    wy = py - fy;
            int ix0 = (int)fx, iy0 = (int)fy;
            int x0 = min(max(ix0,     0), r - 1);
            int x1 = min(max(ix0 + 1, 0), r - 1);
            int y0 = min(max(iy0,     0), r - 1);
            int y1 = min(max(iy0 + 1, 0), r - 1);
            int base = acum[l] + j * r * r;
            float4 c00 = sa[base + y0 * r + x0];
            float4 c01 = sa[base + y0 * r + x1];
            float4 c10 = sa[base + y1 * r + x0];
            float4 c11 = sa[base + y1 * r + x1];
            float w00 = (1.f - wx) * (1.f - wy);
            float w01 = wx * (1.f - wy);
            float w10 = (1.f - wx) * wy;
            float w11 = wx * wy;
            ax += c00.x * w00 + c01.x * w01 + c10.x * w10 + c11.x * w11;
            ay += c00.y * w00 + c01.y * w01 + c10.y * w10 + c11.y * w11;
            az += c00.z * w00 + c01.z * w01 + c10.z * w10 + c11.z * w11;
            aw += c00.w * w00 + c01.w * w01 + c10.w * w10 + c11.w * w11;
        }
        sg[tex] = make_float4(ax, ay, az, aw);
    }
    __syncthreads();

    // ---- Phase 2: sample points; stage outputs in smem; coalesced stores ----
    const int gbase[5] = {GTEX0, GTEX1, GTEX2, GTEX3, GTEX4};
    float4* og = reinterpret_cast<float4*>(out);

    int iter_stride = gridDim.x * NTHR;
    for (int base = blockIdx.x * NTHR; base < npts; base += iter_stride) {
        int p = base + tid;
        float4 res[5];
        bool valid = (p < npts);
        if (valid) {
            // reference math: gx = x*2-1; ix = (gx+1)*0.5*(r-1) -> hx*(r-1)
            float hx = X[p];
            float hy = Y[p];
            #pragma unroll
            for (int l = 0; l < 5; l++) {
                const int r  = resa[l];
                const int n2 = 2 * r;
                float h = hx * (float)(2 * r - 2);   // doubled lattice coord
                float v = hy * (float)(2 * r - 2);
                int m0 = (int)floorf(h);
                int k0 = (int)floorf(v);
                m0 = min(max(m0, 0), n2 - 2);
                k0 = min(max(k0, 0), n2 - 2);
                float wx = h - (float)m0;
                float wy = v - (float)k0;

                const float4* row0 = sg + gbase[l] + k0 * n2 + m0;
                const float4* row1 = row0 + n2;
                float4 c00 = row0[0];
                float4 c01 = row0[1];
                float4 c10 = row1[0];
                float4 c11 = row1[1];

                float w00 = (1.f - wx) * (1.f - wy);
                float w01 = wx * (1.f - wy);
                float w10 = (1.f - wx) * wy;
                float w11 = wx * wy;

                float4 o;
                o.x = c00.x * w00 + c01.x * w01 + c10.x * w10 + c11.x * w11;
                o.y = c00.y * w00 + c01.y * w01 + c10.y * w10 + c11.y * w11;
                o.z = c00.z * w00 + c01.z * w01 + c10.z * w10 + c11.z * w11;
                o.w = c00.w * w00 + c01.w * w01 + c10.w * w10 + c11.w * w11;
                res[l] = o;
            }
        }

        __syncthreads();   // previous iteration's staged reads complete
        if (valid) {
            #pragma unroll
            for (int l = 0; l < 5; l++) sa[tid * 5 + l] = res[l];
        }
        __syncthreads();

        int cnt = min(NTHR, npts - base) * 5;   // float4 count this iter
        float4* dst = og + (size_t)base * 5;
        for (int i = tid; i < cnt; i += NTHR) dst[i] = sa[i];
    }
}

// ---------------------------------------------------------------------------
extern "C" void kernel_launch(void* const* d_in, const int* in_sizes, int n_in,
                              void* d_out, int out_size) {
    const float* X = nullptr;
    const float* Yv = nullptr;
    const float* W = nullptr;
    const float* F[5] = {nullptr, nullptr, nullptr, nullptr, nullptr};
    int npts = 0;

    for (int i = 0; i < n_in; i++) {
        int s = in_sizes[i];
        const float* p = (const float*)d_in[i];
        if (s == 36)        W    = p;
        else if (s == 512)  F[0] = p;
        else if (s == 1152) F[1] = p;
        else if (s == 3200) F[2] = p;
        else if (s == 2592) F[3] = p;
        else if (s == 8192) F[4] = p;
        else {
            if (!X) { X = p; npts = s; }
            else     Yv = p;
        }
    }

    static int nsm = 0;
    static bool attr_set = false;
    if (!attr_set) {
        cudaFuncSetAttribute(k_fused, cudaFuncAttributeMaxDynamicSharedMemorySize, SMEM_BYTES);
        cudaDeviceGetAttribute(&nsm, cudaDevAttrMultiProcessorCount, 0);
        if (nsm <= 0) nsm = 148;
        attr_set = true;
    }

    k_fused<<<nsm, NTHR, SMEM_BYTES>>>(F[0], F[1], F[2], F[3], F[4], W,
                                       X, Yv, (float*)d_out, npts);
}

// round 3
// speedup vs baseline: 1.3060x; 1.3060x over previous
#include <cuda_runtime.h>
#include <cuda_fp16.h>
#include <math.h>

// ---------------------------------------------------------------------------
// Encoder_conv2: 5-level grid encoder, fused single kernel.
//   per level: a = tanh(depthwise_conv3x3(F)); out_l = sum_cell bilinear(a[cell], p+0.5*cell)
// Merged-lattice trick: the 2-cell sum is piecewise bilinear on the half-integer
// lattice -> per level build G[(2r)^2][4ch] once per block (redundant, tiny),
// stored in smem as scaled fp16 (half4/texel, 8 B). Sampling = 4 LDS.64 +
// f32 blend per level per point; direct coalesced-ish STG.128 output.
// Scale 2^10 applied at pack, 2^-10 folded into blend weights (exact pow2).
// ---------------------------------------------------------------------------

#define NTHR 512

// G texel bases: (2r)^2 per level, r = 8,12,20,18,32
#define GTEX0 0
#define GTEX1 256
#define GTEX2 832
#define GTEX3 2432
#define GTEX4 3728
#define GTEXT 7824

#define SCRATCH_F4 2048                    // largest level: 2 cells * 32*32
#define SMEM_BYTES (GTEXT * 8 + SCRATCH_F4 * 16)   // 62592 + 32768 = 95360 B

#define SCALE_UP 1024.0f
#define SCALE_DN (1.0f / 1024.0f)

__global__ void __launch_bounds__(NTHR, 2)
k_fused(const float* __restrict__ F0, const float* __restrict__ F1,
        const float* __restrict__ F2, const float* __restrict__ F3,
        const float* __restrict__ F4, const float* __restrict__ W,
        const float* __restrict__ X, const float* __restrict__ Y,
        float* __restrict__ out, int npts) {
    extern __shared__ unsigned char smraw[];
    uint2*  sg = reinterpret_cast<uint2*>(smraw);              // fp16 grids
    float4* sa = reinterpret_cast<float4*>(smraw + GTEXT * 8); // per-level f32 scratch

    const int tid = threadIdx.x;

    // conv weights (36 floats, broadcast)
    float w[36];
    #pragma unroll
    for (int i = 0; i < 36; i++) w[i] = W[i];

    const float* Fs[5] = {F0, F1, F2, F3, F4};
    const int resa [5] = {8, 12, 20, 18, 32};
    const int gbase[5] = {GTEX0, GTEX1, GTEX2, GTEX3, GTEX4};

    // ---- Prologue: per level, conv3x3+tanh -> sa (f32), then merged grid -> sg (fp16) ----
    #pragma unroll
    for (int l = 0; l < 5; l++) {
        const float* Fl = Fs[l];
        const int r  = resa[l];
        const int rr = r * r;
        const int na = 2 * rr;

        for (int tex = tid; tex < na; tex += NTHR) {
            int j  = tex / rr;
            int yx = tex - j * rr;
            int y  = yx / r;
            int x  = yx - y * r;
            float oc[4];
            #pragma unroll
            for (int c = 0; c < 4; c++) {
                float s = 0.f;
                #pragma unroll
                for (int dy = 0; dy < 3; dy++) {
                    int yy = y + dy - 1;
                    if (yy < 0 || yy >= r) continue;
                    #pragma unroll
                    for (int dx = 0; dx < 3; dx++) {
                        int xx = x + dx - 1;
                        if (xx < 0 || xx >= r) continue;
                        s += __ldg(&Fl[((j * 4 + c) * r + yy) * r + xx]) * w[c * 9 + dy * 3 + dx];
                    }
                }
                oc[c] = tanhf(s);
            }
            sa[tex] = make_float4(oc[0], oc[1], oc[2], oc[3]);
        }
        __syncthreads();

        const int n2 = 2 * r;
        const int ng = n2 * n2;
        for (int tex = tid; tex < ng; tex += NTHR) {
            int k = tex / n2;
            int m = tex - k * n2;
            float ax = 0.f, ay = 0.f, az = 0.f, aw = 0.f;
            #pragma unroll
            for (int j = 0; j < 2; j++) {
                float px = 0.5f * (float)(m + j);
                float py = 0.5f * (float)(k + j);
                float fx = floorf(px), fy = floorf(py);
                float wx = px - fx,    wy = py - fy;
                int ix0 = (int)fx, iy0 = (int)fy;
                int x0 = min(max(ix0,     0), r - 1);
                int x1 = min(max(ix0 + 1, 0), r - 1);
                int y0 = min(max(iy0,     0), r - 1);
                int y1 = min(max(iy0 + 1, 0), r - 1);
                int base = j * rr;
                float4 c00 = sa[base + y0 * r + x0];
                float4 c01 = sa[base + y0 * r + x1];
                float4 c10 = sa[base + y1 * r + x0];
                float4 c11 = sa[base + y1 * r + x1];
                float w00 = (1.f - wx) * (1.f - wy);
                float w01 = wx * (1.f - wy);
                float w10 = (1.f - wx) * wy;
                float w11 = wx * wy;
                ax += c00.x * w00 + c01.x * w01 + c10.x * w10 + c11.x * w11;
                ay += c00.y * w00 + c01.y * w01 + c10.y * w10 + c11.y * w11;
                az += c00.z * w00 + c01.z * w01 + c10.z * w10 + c11.z * w11;
                aw += c00.w * w00 + c01.w * w01 + c10.w * w10 + c11.w * w11;
            }
            __half2 h01 = __floats2half2_rn(ax * SCALE_UP, ay * SCALE_UP);
            __half2 h23 = __floats2half2_rn(az * SCALE_UP, aw * SCALE_UP);
            uint2 packed;
            packed.x = *reinterpret_cast<unsigned int*>(&h01);
            packed.y = *reinterpret_cast<unsigned int*>(&h23);
            sg[gbase[l] + tex] = packed;
        }
        __syncthreads();
    }

    // ---- Sampling: one bilinear fetch (4 LDS.64) per level, f32 blend ----
    const int stride = gridDim.x * NTHR;
    for (int p = blockIdx.x * NTHR + tid; p < npts; p += stride) {
        float hx = __ldg(&X[p]);   // gx=(x*2-1); ix=(gx+1)/2*(r-1) -> hx*(r-1)
        float hy = __ldg(&Y[p]);

        float4 res[5];
        #pragma unroll
        for (int l = 0; l < 5; l++) {
            const int r  = resa[l];
            const int n2 = 2 * r;
            float h = hx * (float)(2 * r - 2);   // doubled (half-int lattice) coords
            float v = hy * (float)(2 * r - 2);
            int m0 = (int)floorf(h);
            int k0 = (int)floorf(v);
            m0 = min(max(m0, 0), n2 - 2);
            k0 = min(max(k0, 0), n2 - 2);
            float wx = h - (float)m0;
            float wy = v - (float)k0;

            const uint2* g = sg + gbase[l] + k0 * n2 + m0;
            uint2 t00 = g[0];
            uint2 t01 = g[1];
            uint2 t10 = g[n2];
            uint2 t11 = g[n2 + 1];

            float2 a00 = __half22float2(*reinterpret_cast<__half2*>(&t00.x));
            float2 b00 = __half22float2(*reinterpret_cast<__half2*>(&t00.y));
            float2 a01 = __half22float2(*reinterpret_cast<__half2*>(&t01.x));
            float2 b01 = __half22float2(*reinterpret_cast<__half2*>(&t01.y));
            float2 a10 = __half22float2(*reinterpret_cast<__half2*>(&t10.x));
            float2 b10 = __half22float2(*reinterpret_cast<__half2*>(&t10.y));
            float2 a11 = __half22float2(*reinterpret_cast<__half2*>(&t11.x));
            float2 b11 = __half22float2(*reinterpret_cast<__half2*>(&t11.y));

            // fold SCALE_DN into the y-weights (exact power of two)
            float wyS = wy * SCALE_DN;
            float wyB = SCALE_DN - wyS;      // (1-wy)*SCALE_DN
            float w00 = (1.f - wx) * wyB;
            float w01 = wx * wyB;
            float w10 = (1.f - wx) * wyS;
            float w11 = wx * wyS;

            float4 o;
            o.x = a00.x * w00 + a01.x * w01 + a10.x * w10 + a11.x * w11;
            o.y = a00.y * w00 + a01.y * w01 + a10.y * w10 + a11.y * w11;
            o.z = b00.x * w00 + b01.x * w01 + b10.x * w10 + b11.x * w11;
            o.w = b00.y * w00 + b01.y * w01 + b10.y * w10 + b11.y * w11;
            res[l] = o;
        }

        float4* op = reinterpret_cast<float4*>(out + (size_t)p * 20);
        #pragma unroll
        for (int l = 0; l < 5; l++) op[l] = res[l];
    }
}

// ---------------------------------------------------------------------------
extern "C" void kernel_launch(void* const* d_in, const int* in_sizes, int n_in,
                              void* d_out, int out_size) {
    const float* X = nullptr;
    const float* Yv = nullptr;
    const float* W = nullptr;
    const float* F[5] = {nullptr, nullptr, nullptr, nullptr, nullptr};
    int npts = 0;

    for (int i = 0; i < n_in; i++) {
        int s = in_sizes[i];
        const float* p = (const float*)d_in[i];
        if (s == 36)        W    = p;
        else if (s == 512)  F[0] = p;
        else if (s == 1152) F[1] = p;
        else if (s == 3200) F[2] = p;
        else if (s == 2592) F[3] = p;
        else if (s == 8192) F[4] = p;
        else {
            if (!X) { X = p; npts = s; }
            else     Yv = p;
        }
    }

    static int nsm = 0;
    static bool init_done = false;
    if (!init_done) {
        cudaFuncSetAttribute(k_fused, cudaFuncAttributeMaxDynamicSharedMemorySize, SMEM_BYTES);
        cudaDeviceGetAttribute(&nsm, cudaDevAttrMultiProcessorCount, 0);
        if (nsm <= 0) nsm = 148;
        init_done = true;
    }

    k_fused<<<2 * nsm, NTHR, SMEM_BYTES>>>(F[0], F[1], F[2], F[3], F[4], W,
                                           X, Yv, (float*)d_out, npts);
}